// round 3
// baseline (speedup 1.0000x reference)
#include <cuda_runtime.h>
#include <cuda_bf16.h>
#include <cstdint>

// out[b, seg[i], d] += v[b, i, d]
// Inputs (metadata order): d_in[0]=data (unused), d_in[1]=v (f32 B*S*D), d_in[2]=segment_index (i32 S)
// Output: f32 B*NUM_SEGMENTS*D
//
// Strategy: one thread per (row, d4) where d4 indexes a float4 of the D=64
// lane dim. Coalesced float4 read of v; vectorized fire-and-forget L2
// reduction red.global.add.v4.f32 into the output (output fits in L2).

static constexpr int D = 64;           // head dim (fixed for this problem)
static constexpr int D4 = D / 4;       // 16 float4 per row

__global__ void __launch_bounds__(256, 8)
seg_sum_kernel(const float4* __restrict__ v,
               const int*    __restrict__ seg,
               float4*       __restrict__ out,
               int S, int num_segments, long total_items)
{
    long tid = (long)blockIdx.x * blockDim.x + threadIdx.x;
    if (tid >= total_items) return;

    int  d4  = (int)(tid & (D4 - 1));
    long row = tid >> 4;               // global row index in [0, B*S)
    int  i   = (int)(row % S);         // position within sequence
    long b   = row / S;                // batch

    int s = __ldg(seg + i);

    float4 val = v[row * D4 + d4];

    float4* dst = out + ((b * num_segments + s) * D4 + d4);
    asm volatile(
        "red.global.add.v4.f32 [%0], {%1, %2, %3, %4};"
        :: "l"(dst), "f"(val.x), "f"(val.y), "f"(val.z), "f"(val.w)
        : "memory");
}

extern "C" void kernel_launch(void* const* d_in, const int* in_sizes, int n_in,
                              void* d_out, int out_size)
{
    const float* v   = (const float*)d_in[1];
    const int*   seg = (const int*)d_in[2];
    float*       out = (float*)d_out;

    int  S     = in_sizes[2];                       // 200000
    long vN    = (long)in_sizes[1];                 // B*S*D
    int  B     = (int)(vN / ((long)S * D));         // 4
    int  nseg  = (int)((long)out_size / ((long)B * D)); // 10000

    // Zero the output (harness poisons it with 0xAA).
    cudaMemsetAsync(d_out, 0, (size_t)out_size * sizeof(float), 0);

    long total_items = (long)B * S * D4;            // 12.8M threads
    int  threads = 256;
    long blocks  = (total_items + threads - 1) / threads;

    seg_sum_kernel<<<(unsigned)blocks, threads>>>(
        (const float4*)v, seg, (float4*)out, S, nseg, total_items);
}

// round 8
// speedup vs baseline: 1.0818x; 1.0818x over previous
#include <cuda_runtime.h>
#include <cuda_bf16.h>
#include <cstdint>

// out[b, seg[i], d] += v[b, i, d]
// Inputs: d_in[0]=data (unused), d_in[1]=v (f32 B*S*D), d_in[2]=segment_index (i32 S)
// Output: f32 B*NUM_SEGMENTS*D
//
// R4: batch moved to blockIdx.y (kills the 64-bit runtime div/mod that made
// alu pipe 30.7%), and each thread handles 2 float4 (d4, d4+8) of one row,
// halving thread count / index overhead and doubling load MLP.

static constexpr int D  = 64;
static constexpr int D4 = D / 4;     // 16 float4 per row
static constexpr int FPT = 2;        // float4 per thread
static constexpr int TPR = D4 / FPT; // 8 threads per row

__global__ void __launch_bounds__(256, 8)
seg_sum_kernel(const float4* __restrict__ v,
               const int*    __restrict__ seg,
               float4*       __restrict__ out,
               int S, int num_segments)
{
    int  b    = blockIdx.y;
    long gtid = (long)blockIdx.x * blockDim.x + threadIdx.x; // within batch
    int  i    = (int)(gtid >> 3);        // row within sequence
    int  d4   = (int)(gtid & (TPR - 1)); // 0..7
    if (i >= S) return;

    int s = __ldg(seg + i);

    const float4* src = v + ((long)b * S + i) * D4 + d4;
    float4 a0 = src[0];
    float4 a1 = src[TPR];

    float4* dst = out + ((long)b * num_segments + s) * D4 + d4;
    asm volatile(
        "red.global.add.v4.f32 [%0], {%1, %2, %3, %4};"
        :: "l"(dst), "f"(a0.x), "f"(a0.y), "f"(a0.z), "f"(a0.w)
        : "memory");
    asm volatile(
        "red.global.add.v4.f32 [%0], {%1, %2, %3, %4};"
        :: "l"(dst + TPR), "f"(a1.x), "f"(a1.y), "f"(a1.z), "f"(a1.w)
        : "memory");
}

extern "C" void kernel_launch(void* const* d_in, const int* in_sizes, int n_in,
                              void* d_out, int out_size)
{
    const float* v   = (const float*)d_in[1];
    const int*   seg = (const int*)d_in[2];

    int  S    = in_sizes[2];                            // 200000
    long vN   = (long)in_sizes[1];                      // B*S*D
    int  B    = (int)(vN / ((long)S * D));              // 4
    int  nseg = (int)((long)out_size / ((long)B * D));  // 10000

    cudaMemsetAsync(d_out, 0, (size_t)out_size * sizeof(float), 0);

    long per_batch = (long)S * TPR;                     // 1.6M threads/batch
    int  threads   = 256;
    dim3 grid((unsigned)((per_batch + threads - 1) / threads), (unsigned)B, 1);

    seg_sum_kernel<<<grid, threads>>>(
        (const float4*)v, seg, (float4*)d_out, S, nseg);
}